// round 4
// baseline (speedup 1.0000x reference)
#include <cuda_runtime.h>
#include <cstdint>

// Problem constants
#define NN 50000
#define EE 800000
#define FF 64      // node feature dim
#define HH 64      // hidden
#define H2 128     // 2*H
#define CC 40      // classes
#define LL 3

#define BN_EPS 1e-5f

// -------- device scratch (no allocations allowed) --------
__device__ __align__(16) float g_x[NN * FF];     // current node features
__device__ __align__(16) float g_agg[NN * FF];   // neighbor-sum buffer
__device__ int   g_is32;                          // 1 if edge_index is int32

// ---------------------------------------------------------------------------
// Detect edge_index dtype: if the data is really int32, reading int64 words
// combines two indices -> values outside [0, NN) appear.
// ---------------------------------------------------------------------------
__global__ void detect_kernel(const long long* __restrict__ ei) {
    int is32 = 0;
    for (int i = 0; i < 256; i++) {
        long long v = ei[i];
        if (v < 0 || v >= NN) { is32 = 1; break; }
    }
    g_is32 = is32;
}

// ---------------------------------------------------------------------------
// Scatter-add: agg[dst] += x[src] for every edge.
// One thread per (edge, float4-chunk): 16 chunks cover 64 floats.
// red.global.add.v4.f32 (sm_90+): 4x fewer L2 atomic ops than scalar.
// ---------------------------------------------------------------------------
__global__ void scatter_kernel(const void* __restrict__ ei,
                               const float* __restrict__ xin,
                               float* __restrict__ agg) {
    long long idx = (long long)blockIdx.x * blockDim.x + threadIdx.x;
    if (idx >= (long long)EE * 16) return;
    int e  = (int)(idx >> 4);
    int f4 = (int)(idx & 15);

    int src, dst;
    if (g_is32) {
        const int* p = (const int*)ei;
        src = __ldg(p + e);
        dst = __ldg(p + EE + e);
    } else {
        const long long* p = (const long long*)ei;
        src = (int)__ldg(p + e);
        dst = (int)__ldg(p + EE + e);
    }
    // Defensive: never fault on bad indices (mis-detection shows as rel_err).
    if ((unsigned)src >= NN || (unsigned)dst >= NN) return;

    const float4 v = *(const float4*)(xin + (long long)src * FF + f4 * 4);
    float* a = agg + (long long)dst * FF + f4 * 4;
    asm volatile("red.global.add.v4.f32 [%0], {%1,%2,%3,%4};"
                 :: "l"(a), "f"(v.x), "f"(v.y), "f"(v.z), "f"(v.w)
                 : "memory");
}

// ---------------------------------------------------------------------------
// Fused GIN layer MLP:
//   h = agg + x
//   t = relu(bn1(h @ W1 + b1))        (64 -> 128)
//   x' = relu(bn2(t @ W2 + b2))       (128 -> 64)
// BN folded into affine: a = g*rsqrt(v+eps), c = (bias - m)*a + beta.
// Shared floats: W1 8192 + W2 8192 + a1 128 + c1 128 + a2 64 + c2 64
//              + xs 4096 + hs 8192 = 29056 floats = 116224 B   (FIXED: was
//              28864 -> hs overran the allocation by 768 B -> illegal access)
// ---------------------------------------------------------------------------
#define MLP_SHM_FLOATS 29056
#define MLP_SHM_BYTES  (MLP_SHM_FLOATS * 4)

__global__ __launch_bounds__(512) void mlp_kernel(
    const float* __restrict__ agg, const float* __restrict__ xin,
    const float* __restrict__ W1, const float* __restrict__ b1,
    const float* __restrict__ g1, const float* __restrict__ bt1,
    const float* __restrict__ m1, const float* __restrict__ v1,
    const float* __restrict__ W2, const float* __restrict__ b2,
    const float* __restrict__ gc, const float* __restrict__ bc,
    const float* __restrict__ mc, const float* __restrict__ vc,
    float* __restrict__ xout)
{
    extern __shared__ float sm[];
    float* W1s = sm;             // [64][128]   8192
    float* W2s = W1s + 8192;     // [128][64]   8192
    float* a1  = W2s + 8192;     // [128]
    float* c1  = a1 + 128;       // [128]
    float* a2  = c1 + 128;       // [64]
    float* c2  = a2 + 64;        // [64]
    float* xs  = c2 + 64;        // [64][64]    4096
    float* hs  = xs + 4096;      // [64][128]   8192   (ends at 29056)

    const int tid = threadIdx.x;

    for (int i = tid; i < 8192; i += 512) W1s[i] = W1[i];
    for (int i = tid; i < 8192; i += 512) W2s[i] = W2[i];
    if (tid < 128) {
        float a = g1[tid] * rsqrtf(v1[tid] + BN_EPS);
        a1[tid] = a;
        c1[tid] = (b1[tid] - m1[tid]) * a + bt1[tid];
    } else if (tid < 192) {
        int j = tid - 128;
        float a = gc[j] * rsqrtf(vc[j] + BN_EPS);
        a2[j] = a;
        c2[j] = (b2[j] - mc[j]) * a + bc[j];
    }
    __syncthreads();

    const int ntiles = (NN + 63) >> 6;
    for (int tile = blockIdx.x; tile < ntiles; tile += gridDim.x) {
        const int base   = tile << 6;
        const int nvalid = min(64, NN - base);

        // h = agg + x  -> shared
        for (int i = tid; i < 64 * 64; i += 512) {
            int node = i >> 6;
            xs[i] = (node < nvalid) ? (agg[(long long)base * 64 + i] +
                                       xin[(long long)base * 64 + i]) : 0.0f;
        }
        __syncthreads();

        // GEMM1: [64 x 64] @ [64 x 128]
        for (int o = tid; o < 64 * 128; o += 512) {
            int node = o >> 7, j = o & 127;
            const float* xr = xs + node * 64;
            float acc = 0.0f;
            #pragma unroll
            for (int k = 0; k < 64; k++)
                acc = fmaf(xr[k], W1s[k * 128 + j], acc);
            hs[o] = fmaxf(acc * a1[j] + c1[j], 0.0f);
        }
        __syncthreads();

        // GEMM2: [64 x 128] @ [128 x 64] -> xout
        for (int o = tid; o < 64 * 64; o += 512) {
            int node = o >> 6, j = o & 63;
            const float* hr = hs + node * 128;
            float acc = 0.0f;
            #pragma unroll
            for (int k = 0; k < 128; k++)
                acc = fmaf(hr[k], W2s[k * 64 + j], acc);
            if (node < nvalid)
                xout[(long long)base * 64 + o] = fmaxf(acc * a2[j] + c2[j], 0.0f);
        }
        __syncthreads();
    }
}

// ---------------------------------------------------------------------------
// Head: t = relu(bn(x @ lin1 + b)); logits = t @ lin2 + b2; log_softmax.
// Shared floats: 4096+2560+64+64+40+4096+4096+2560 = 17576 (verified)
// ---------------------------------------------------------------------------
#define HEAD_SHM_FLOATS 17576
#define HEAD_SHM_BYTES  (HEAD_SHM_FLOATS * 4)

__global__ __launch_bounds__(512) void head_kernel(
    const float* __restrict__ x,
    const float* __restrict__ lin1_W, const float* __restrict__ lin1_b,
    const float* __restrict__ g,  const float* __restrict__ b,
    const float* __restrict__ m,  const float* __restrict__ v,
    const float* __restrict__ lin2_W, const float* __restrict__ lin2_b,
    float* __restrict__ out)
{
    extern __shared__ float sm[];
    float* W1s = sm;             // [64][64]
    float* W2s = W1s + 4096;     // [64][40]
    float* a1  = W2s + 2560;     // [64]
    float* c1  = a1 + 64;        // [64]
    float* c2  = c1 + 64;        // [40]
    float* xs  = c2 + 40;        // [64][64]
    float* ts  = xs + 4096;      // [64][64]
    float* ls  = ts + 4096;      // [64][40]

    const int tid = threadIdx.x;

    for (int i = tid; i < 4096; i += 512) W1s[i] = lin1_W[i];
    for (int i = tid; i < 2560; i += 512) W2s[i] = lin2_W[i];
    if (tid < 64) {
        float a = g[tid] * rsqrtf(v[tid] + BN_EPS);
        a1[tid] = a;
        c1[tid] = (lin1_b[tid] - m[tid]) * a + b[tid];
    } else if (tid < 104) {
        c2[tid - 64] = lin2_b[tid - 64];
    }
    __syncthreads();

    const int ntiles = (NN + 63) >> 6;
    for (int tile = blockIdx.x; tile < ntiles; tile += gridDim.x) {
        const int base   = tile << 6;
        const int nvalid = min(64, NN - base);

        for (int i = tid; i < 64 * 64; i += 512) {
            int node = i >> 6;
            xs[i] = (node < nvalid) ? x[(long long)base * 64 + i] : 0.0f;
        }
        __syncthreads();

        // lin1 + bn + relu
        for (int o = tid; o < 64 * 64; o += 512) {
            int node = o >> 6, j = o & 63;
            const float* xr = xs + node * 64;
            float acc = 0.0f;
            #pragma unroll
            for (int k = 0; k < 64; k++)
                acc = fmaf(xr[k], W1s[k * 64 + j], acc);
            ts[o] = fmaxf(acc * a1[j] + c1[j], 0.0f);
        }
        __syncthreads();

        // lin2 -> logits
        for (int o = tid; o < 64 * CC; o += 512) {
            int node = o / CC, j = o - node * CC;
            const float* tr = ts + node * 64;
            float acc = c2[j];
            #pragma unroll
            for (int k = 0; k < 64; k++)
                acc = fmaf(tr[k], W2s[k * CC + j], acc);
            ls[o] = acc;
        }
        __syncthreads();

        // log_softmax per node
        if (tid < 64 && tid < nvalid) {
            const float* lr = ls + tid * CC;
            float mx = lr[0];
            #pragma unroll
            for (int c = 1; c < CC; c++) mx = fmaxf(mx, lr[c]);
            float s = 0.0f;
            #pragma unroll
            for (int c = 0; c < CC; c++) s += expf(lr[c] - mx);
            float lse = mx + logf(s);
            float* orow = out + (long long)(base + tid) * CC;
            #pragma unroll
            for (int c = 0; c < CC; c++) orow[c] = lr[c] - lse;
        }
        __syncthreads();
    }
}

// ---------------------------------------------------------------------------
// Inputs resolved BY ELEMENT COUNT (order-proof). Equal-size groups keep
// declared relative order.
// ---------------------------------------------------------------------------
extern "C" void kernel_launch(void* const* d_in, const int* in_sizes, int n_in,
                              void* d_out, int out_size) {
    const float* x = nullptr;
    const void*  ei = nullptr;
    const float* w24[2] = {nullptr, nullptr}; int n24 = 0;
    const float* p384[5] = {0};               int n384 = 0;
    const float* p192[5] = {0};               int n192 = 0;
    const float* p64[5]  = {0};               int n64 = 0;
    const float* lin1_W = nullptr;
    const float* lin2_W = nullptr;
    const float* lin2_b = nullptr;

    for (int i = 0; i < n_in; i++) {
        int s = in_sizes[i];
        const float* p = (const float*)d_in[i];
        if      (s == NN * FF)     x = p;
        else if (s == 2 * EE)      ei = d_in[i];
        else if (s == LL * FF * H2) { if (n24 < 2) w24[n24++] = p; }
        else if (s == LL * H2)     { if (n384 < 5) p384[n384++] = p; }
        else if (s == LL * HH)     { if (n192 < 5) p192[n192++] = p; }
        else if (s == HH * HH)     lin1_W = p;
        else if (s == HH)          { if (n64 < 5) p64[n64++] = p; }
        else if (s == HH * CC)     lin2_W = p;
        else if (s == CC)          lin2_b = p;
    }

    const float* W1s  = w24[0];
    const float* W2s  = w24[1];
    const float* b1s  = p384[0], *g1s = p384[1], *bt1s = p384[2],
               * m1s  = p384[3], *v1s = p384[4];
    const float* b2s  = p192[0], *gcs = p192[1], *bcs = p192[2],
               * mcs  = p192[3], *vcs = p192[4];
    const float* lin1_b = p64[0], *g_bn1 = p64[1], *b_bn1 = p64[2],
               * m_bn1  = p64[3], *v_bn1 = p64[4];

    if (!x || !ei || !W1s || !W2s || !lin1_W || !lin2_W || !lin2_b) return;

    float* gx;   cudaGetSymbolAddress((void**)&gx,  g_x);
    float* gagg; cudaGetSymbolAddress((void**)&gagg, g_agg);

    cudaFuncSetAttribute(mlp_kernel,  cudaFuncAttributeMaxDynamicSharedMemorySize, MLP_SHM_BYTES);
    cudaFuncSetAttribute(head_kernel, cudaFuncAttributeMaxDynamicSharedMemorySize, HEAD_SHM_BYTES);

    detect_kernel<<<1, 1>>>((const long long*)ei);
    cudaMemcpyAsync(gx, x, (size_t)NN * FF * sizeof(float), cudaMemcpyDeviceToDevice);

    const long long sc_threads = (long long)EE * 16;
    const int sc_blocks = (int)((sc_threads + 255) / 256);

    for (int l = 0; l < LL; l++) {
        cudaMemsetAsync(gagg, 0, (size_t)NN * FF * sizeof(float));
        scatter_kernel<<<sc_blocks, 256>>>(ei, gx, gagg);
        mlp_kernel<<<148, 512, MLP_SHM_BYTES>>>(
            gagg, gx,
            W1s + (size_t)l * FF * H2,  b1s + (size_t)l * H2,
            g1s + (size_t)l * H2,       bt1s + (size_t)l * H2,
            m1s + (size_t)l * H2,       v1s + (size_t)l * H2,
            W2s + (size_t)l * H2 * HH,  b2s + (size_t)l * HH,
            gcs + (size_t)l * HH,       bcs + (size_t)l * HH,
            mcs + (size_t)l * HH,       vcs + (size_t)l * HH,
            gx);
    }

    head_kernel<<<148, 512, HEAD_SHM_BYTES>>>(
        gx, lin1_W, lin1_b, g_bn1, b_bn1, m_bn1, v_bn1, lin2_W, lin2_b,
        (float*)d_out);
}

// round 5
// speedup vs baseline: 1.4117x; 1.4117x over previous
#include <cuda_runtime.h>
#include <cstdint>

#define NN 50000
#define EE 800000
#define FF 64
#define HH 64
#define H2 128
#define CC 40
#define LL 3
#define BN_EPS 1e-5f

__device__ __align__(16) float g_x[NN * FF];     // current node features
__device__ __align__(16) float g_agg[NN * FF];   // x + neighbor-sum buffer
__device__ int   g_is32;

// ---------------------------------------------------------------------------
__global__ void detect_kernel(const long long* __restrict__ ei) {
    int is32 = 0;
    for (int i = 0; i < 256; i++) {
        long long v = ei[i];
        if (v < 0 || v >= NN) { is32 = 1; break; }
    }
    g_is32 = is32;
}

// ---------------------------------------------------------------------------
// Scatter-add: agg[dst] += x[src]; agg pre-seeded with x (GIN eps=0 fusion).
// ---------------------------------------------------------------------------
__global__ void scatter_kernel(const void* __restrict__ ei,
                               const float* __restrict__ xin,
                               float* __restrict__ agg) {
    long long idx = (long long)blockIdx.x * blockDim.x + threadIdx.x;
    if (idx >= (long long)EE * 16) return;
    int e  = (int)(idx >> 4);
    int f4 = (int)(idx & 15);

    int src, dst;
    if (g_is32) {
        const int* p = (const int*)ei;
        src = __ldg(p + e);
        dst = __ldg(p + EE + e);
    } else {
        const long long* p = (const long long*)ei;
        src = (int)__ldg(p + e);
        dst = (int)__ldg(p + EE + e);
    }
    if ((unsigned)src >= NN || (unsigned)dst >= NN) return;

    const float4 v = *(const float4*)(xin + (long long)src * FF + f4 * 4);
    float* a = agg + (long long)dst * FF + f4 * 4;
    asm volatile("red.global.add.v4.f32 [%0], {%1,%2,%3,%4};"
                 :: "l"(a), "f"(v.x), "f"(v.y), "f"(v.z), "f"(v.w)
                 : "memory");
}

// ---------------------------------------------------------------------------
// Register-tiled fused GIN MLP.
//   in:  hin = x + agg      [NN][64]
//   t  = relu(bn1(hin @ W1))    64 -> 128
//   out= relu(bn2(t @ W2))      128 -> 64
// Tile: 128 nodes / block, 512 threads = 16 warps.
// Warp w owns nodes w*8 .. w*8+7.
//   GEMM1: lane covers cols j0=lane*4 (float4 acc per node)
//   GEMM2: lane covers cols j0=lane*2 (float2 acc per node)
// W loads: vector LDS, conflict-free. x loads: warp-uniform (broadcast).
// Shared: W1 8192 + W2 8192 + a1/c1/a2/c2 384 + xs 8192 + hs 16384
//       = 41344 floats = 165376 B
// ---------------------------------------------------------------------------
#define MLP_SHM_FLOATS 41344
#define MLP_SHM_BYTES  (MLP_SHM_FLOATS * 4)

__global__ __launch_bounds__(512) void mlp_kernel(
    const float* __restrict__ hin,
    const float* __restrict__ W1, const float* __restrict__ b1,
    const float* __restrict__ g1, const float* __restrict__ bt1,
    const float* __restrict__ m1, const float* __restrict__ v1,
    const float* __restrict__ W2, const float* __restrict__ b2,
    const float* __restrict__ gc, const float* __restrict__ bc,
    const float* __restrict__ mc, const float* __restrict__ vc,
    float* __restrict__ xout)
{
    extern __shared__ float sm[];
    float* W1s = sm;             // [64][128]   8192
    float* W2s = W1s + 8192;     // [128][64]   8192
    float* a1  = W2s + 8192;     // [128]
    float* c1  = a1 + 128;       // [128]
    float* a2  = c1 + 128;       // [64]
    float* c2  = a2 + 64;        // [64]
    float* xs  = c2 + 64;        // [128][64]   8192
    float* hs  = xs + 8192;      // [128][128]  16384

    const int tid  = threadIdx.x;
    const int warp = tid >> 5;
    const int lane = tid & 31;

    for (int i = tid; i < 8192; i += 512) W1s[i] = W1[i];
    for (int i = tid; i < 8192; i += 512) W2s[i] = W2[i];
    if (tid < 128) {
        float a = g1[tid] * rsqrtf(v1[tid] + BN_EPS);
        a1[tid] = a;
        c1[tid] = (b1[tid] - m1[tid]) * a + bt1[tid];
    } else if (tid < 192) {
        int j = tid - 128;
        float a = gc[j] * rsqrtf(vc[j] + BN_EPS);
        a2[j] = a;
        c2[j] = (b2[j] - mc[j]) * a + bc[j];
    }
    __syncthreads();

    const int ntiles = (NN + 127) >> 7;
    for (int tile = blockIdx.x; tile < ntiles; tile += gridDim.x) {
        const int base = tile << 7;

        // load x tile: 128 rows x 16 float4
        for (int i = tid; i < 2048; i += 512) {
            int node = i >> 4;
            float4 v;
            if (base + node < NN)
                v = *(const float4*)(hin + (size_t)(base + node) * 64 + (i & 15) * 4);
            else
                v = make_float4(0.f, 0.f, 0.f, 0.f);
            *(float4*)(xs + i * 4) = v;
        }
        __syncthreads();

        // ---- GEMM1: [128x64] @ [64x128] -> hs, bn+relu ----
        {
            const int j0 = lane * 4;
            float4 acc[8];
            #pragma unroll
            for (int n = 0; n < 8; n++) acc[n] = make_float4(0.f, 0.f, 0.f, 0.f);
            const float* xrow = xs + (warp * 8) * 64;

            for (int k4 = 0; k4 < 16; k4++) {
                const float4 w0 = *(const float4*)(W1s + (k4 * 4 + 0) * 128 + j0);
                const float4 w1 = *(const float4*)(W1s + (k4 * 4 + 1) * 128 + j0);
                const float4 w2 = *(const float4*)(W1s + (k4 * 4 + 2) * 128 + j0);
                const float4 w3 = *(const float4*)(W1s + (k4 * 4 + 3) * 128 + j0);
                #pragma unroll
                for (int n = 0; n < 8; n++) {
                    const float4 xv = *(const float4*)(xrow + n * 64 + k4 * 4);
                    acc[n].x = fmaf(xv.x, w0.x, acc[n].x);
                    acc[n].y = fmaf(xv.x, w0.y, acc[n].y);
                    acc[n].z = fmaf(xv.x, w0.z, acc[n].z);
                    acc[n].w = fmaf(xv.x, w0.w, acc[n].w);
                    acc[n].x = fmaf(xv.y, w1.x, acc[n].x);
                    acc[n].y = fmaf(xv.y, w1.y, acc[n].y);
                    acc[n].z = fmaf(xv.y, w1.z, acc[n].z);
                    acc[n].w = fmaf(xv.y, w1.w, acc[n].w);
                    acc[n].x = fmaf(xv.z, w2.x, acc[n].x);
                    acc[n].y = fmaf(xv.z, w2.y, acc[n].y);
                    acc[n].z = fmaf(xv.z, w2.z, acc[n].z);
                    acc[n].w = fmaf(xv.z, w2.w, acc[n].w);
                    acc[n].x = fmaf(xv.w, w3.x, acc[n].x);
                    acc[n].y = fmaf(xv.w, w3.y, acc[n].y);
                    acc[n].z = fmaf(xv.w, w3.z, acc[n].z);
                    acc[n].w = fmaf(xv.w, w3.w, acc[n].w);
                }
            }
            const float4 A = *(const float4*)(a1 + j0);
            const float4 C = *(const float4*)(c1 + j0);
            #pragma unroll
            for (int n = 0; n < 8; n++) {
                float4 h;
                h.x = fmaxf(fmaf(acc[n].x, A.x, C.x), 0.f);
                h.y = fmaxf(fmaf(acc[n].y, A.y, C.y), 0.f);
                h.z = fmaxf(fmaf(acc[n].z, A.z, C.z), 0.f);
                h.w = fmaxf(fmaf(acc[n].w, A.w, C.w), 0.f);
                *(float4*)(hs + (warp * 8 + n) * 128 + j0) = h;
            }
        }
        __syncthreads();

        // ---- GEMM2: [128x128] @ [128x64] -> xout, bn+relu ----
        {
            const int j0 = lane * 2;
            float2 acc[8];
            #pragma unroll
            for (int n = 0; n < 8; n++) acc[n] = make_float2(0.f, 0.f);
            const float* hrow = hs + (warp * 8) * 128;

            for (int k4 = 0; k4 < 32; k4++) {
                const float2 w0 = *(const float2*)(W2s + (k4 * 4 + 0) * 64 + j0);
                const float2 w1 = *(const float2*)(W2s + (k4 * 4 + 1) * 64 + j0);
                const float2 w2 = *(const float2*)(W2s + (k4 * 4 + 2) * 64 + j0);
                const float2 w3 = *(const float2*)(W2s + (k4 * 4 + 3) * 64 + j0);
                #pragma unroll
                for (int n = 0; n < 8; n++) {
                    const float4 hv = *(const float4*)(hrow + n * 128 + k4 * 4);
                    acc[n].x = fmaf(hv.x, w0.x, acc[n].x);
                    acc[n].y = fmaf(hv.x, w0.y, acc[n].y);
                    acc[n].x = fmaf(hv.y, w1.x, acc[n].x);
                    acc[n].y = fmaf(hv.y, w1.y, acc[n].y);
                    acc[n].x = fmaf(hv.z, w2.x, acc[n].x);
                    acc[n].y = fmaf(hv.z, w2.y, acc[n].y);
                    acc[n].x = fmaf(hv.w, w3.x, acc[n].x);
                    acc[n].y = fmaf(hv.w, w3.y, acc[n].y);
                }
            }
            const float A0 = a2[j0],     A1 = a2[j0 + 1];
            const float C0 = c2[j0],     C1 = c2[j0 + 1];
            #pragma unroll
            for (int n = 0; n < 8; n++) {
                const int node = base + warp * 8 + n;
                if (node < NN) {
                    float2 o;
                    o.x = fmaxf(fmaf(acc[n].x, A0, C0), 0.f);
                    o.y = fmaxf(fmaf(acc[n].y, A1, C1), 0.f);
                    *(float2*)(xout + (size_t)node * 64 + j0) = o;
                }
            }
        }
        __syncthreads();
    }
}

// ---------------------------------------------------------------------------
// Head: t = relu(bn(x @ lin1 + b)); logits = t @ lin2 + b2; log_softmax.
// ---------------------------------------------------------------------------
#define HEAD_SHM_FLOATS 17576
#define HEAD_SHM_BYTES  (HEAD_SHM_FLOATS * 4)

__global__ __launch_bounds__(512) void head_kernel(
    const float* __restrict__ x,
    const float* __restrict__ lin1_W, const float* __restrict__ lin1_b,
    const float* __restrict__ g,  const float* __restrict__ b,
    const float* __restrict__ m,  const float* __restrict__ v,
    const float* __restrict__ lin2_W, const float* __restrict__ lin2_b,
    float* __restrict__ out)
{
    extern __shared__ float sm[];
    float* W1s = sm;             // [64][64]
    float* W2s = W1s + 4096;     // [64][40]
    float* a1  = W2s + 2560;     // [64]
    float* c1  = a1 + 64;        // [64]
    float* c2  = c1 + 64;        // [40]
    float* xs  = c2 + 40;        // [64][64]
    float* ts  = xs + 4096;      // [64][64]
    float* ls  = ts + 4096;      // [64][40]

    const int tid = threadIdx.x;

    for (int i = tid; i < 4096; i += 512) W1s[i] = lin1_W[i];
    for (int i = tid; i < 2560; i += 512) W2s[i] = lin2_W[i];
    if (tid < 64) {
        float a = g[tid] * rsqrtf(v[tid] + BN_EPS);
        a1[tid] = a;
        c1[tid] = (lin1_b[tid] - m[tid]) * a + b[tid];
    } else if (tid < 104) {
        c2[tid - 64] = lin2_b[tid - 64];
    }
    __syncthreads();

    const int ntiles = (NN + 63) >> 6;
    for (int tile = blockIdx.x; tile < ntiles; tile += gridDim.x) {
        const int base   = tile << 6;
        const int nvalid = min(64, NN - base);

        for (int i = tid; i < 64 * 64; i += 512) {
            int node = i >> 6;
            xs[i] = (node < nvalid) ? x[(long long)base * 64 + i] : 0.0f;
        }
        __syncthreads();

        for (int o = tid; o < 64 * 64; o += 512) {
            int node = o >> 6, j = o & 63;
            const float* xr = xs + node * 64;
            float acc = 0.0f;
            #pragma unroll
            for (int k = 0; k < 64; k++)
                acc = fmaf(xr[k], W1s[k * 64 + j], acc);
            ts[o] = fmaxf(acc * a1[j] + c1[j], 0.0f);
        }
        __syncthreads();

        for (int o = tid; o < 64 * CC; o += 512) {
            int node = o / CC, j = o - node * CC;
            const float* tr = ts + node * 64;
            float acc = c2[j];
            #pragma unroll
            for (int k = 0; k < 64; k++)
                acc = fmaf(tr[k], W2s[k * CC + j], acc);
            ls[o] = acc;
        }
        __syncthreads();

        if (tid < 64 && tid < nvalid) {
            const float* lr = ls + tid * CC;
            float mx = lr[0];
            #pragma unroll
            for (int c = 1; c < CC; c++) mx = fmaxf(mx, lr[c]);
            float s = 0.0f;
            #pragma unroll
            for (int c = 0; c < CC; c++) s += expf(lr[c] - mx);
            float lse = mx + logf(s);
            float* orow = out + (long long)(base + tid) * CC;
            #pragma unroll
            for (int c = 0; c < CC; c++) orow[c] = lr[c] - lse;
        }
        __syncthreads();
    }
}

// ---------------------------------------------------------------------------
extern "C" void kernel_launch(void* const* d_in, const int* in_sizes, int n_in,
                              void* d_out, int out_size) {
    const float* x = nullptr;
    const void*  ei = nullptr;
    const float* w24[2] = {nullptr, nullptr}; int n24 = 0;
    const float* p384[5] = {0};               int n384 = 0;
    const float* p192[5] = {0};               int n192 = 0;
    const float* p64[5]  = {0};               int n64 = 0;
    const float* lin1_W = nullptr;
    const float* lin2_W = nullptr;
    const float* lin2_b = nullptr;

    for (int i = 0; i < n_in; i++) {
        int s = in_sizes[i];
        const float* p = (const float*)d_in[i];
        if      (s == NN * FF)     x = p;
        else if (s == 2 * EE)      ei = d_in[i];
        else if (s == LL * FF * H2) { if (n24 < 2) w24[n24++] = p; }
        else if (s == LL * H2)     { if (n384 < 5) p384[n384++] = p; }
        else if (s == LL * HH)     { if (n192 < 5) p192[n192++] = p; }
        else if (s == HH * HH)     lin1_W = p;
        else if (s == HH)          { if (n64 < 5) p64[n64++] = p; }
        else if (s == HH * CC)     lin2_W = p;
        else if (s == CC)          lin2_b = p;
    }

    const float* W1s  = w24[0];
    const float* W2s  = w24[1];
    const float* b1s  = p384[0], *g1s = p384[1], *bt1s = p384[2],
               * m1s  = p384[3], *v1s = p384[4];
    const float* b2s  = p192[0], *gcs = p192[1], *bcs = p192[2],
               * mcs  = p192[3], *vcs = p192[4];
    const float* lin1_b = p64[0], *g_bn1 = p64[1], *b_bn1 = p64[2],
               * m_bn1  = p64[3], *v_bn1 = p64[4];

    if (!x || !ei || !W1s || !W2s || !lin1_W || !lin2_W || !lin2_b) return;

    float* gx;   cudaGetSymbolAddress((void**)&gx,  g_x);
    float* gagg; cudaGetSymbolAddress((void**)&gagg, g_agg);

    cudaFuncSetAttribute(mlp_kernel,  cudaFuncAttributeMaxDynamicSharedMemorySize, MLP_SHM_BYTES);
    cudaFuncSetAttribute(head_kernel, cudaFuncAttributeMaxDynamicSharedMemorySize, HEAD_SHM_BYTES);

    detect_kernel<<<1, 1>>>((const long long*)ei);
    cudaMemcpyAsync(gx, x, (size_t)NN * FF * sizeof(float), cudaMemcpyDeviceToDevice);

    const long long sc_threads = (long long)EE * 16;
    const int sc_blocks = (int)((sc_threads + 255) / 256);

    for (int l = 0; l < LL; l++) {
        // seed agg with x (GIN eps=0: h = x + sum_neighbors), then scatter-add
        cudaMemcpyAsync(gagg, gx, (size_t)NN * FF * sizeof(float),
                        cudaMemcpyDeviceToDevice);
        scatter_kernel<<<sc_blocks, 256>>>(ei, gx, gagg);
        mlp_kernel<<<148, 512, MLP_SHM_BYTES>>>(
            gagg,
            W1s + (size_t)l * FF * H2,  b1s + (size_t)l * H2,
            g1s + (size_t)l * H2,       bt1s + (size_t)l * H2,
            m1s + (size_t)l * H2,       v1s + (size_t)l * H2,
            W2s + (size_t)l * H2 * HH,  b2s + (size_t)l * HH,
            gcs + (size_t)l * HH,       bcs + (size_t)l * HH,
            mcs + (size_t)l * HH,       vcs + (size_t)l * HH,
            gx);
    }

    head_kernel<<<148, 512, HEAD_SHM_BYTES>>>(
        gx, lin1_W, lin1_b, g_bn1, b_bn1, m_bn1, v_bn1, lin2_W, lin2_b,
        (float*)d_out);
}

// round 6
// speedup vs baseline: 1.4527x; 1.0290x over previous
#include <cuda_runtime.h>
#include <cstdint>

#define NN 50000
#define EE 800000
#define FF 64
#define HH 64
#define H2 128
#define CC 40
#define LL 3
#define BN_EPS 1e-5f

__device__ __align__(16) float g_x[NN * FF];     // current node features
__device__ __align__(16) float g_agg[NN * FF];   // x + neighbor-sum buffer
__device__ int g_is32;

// CSR scratch
__device__ int g_cnt[NN];          // per-node in-degree (count pass)
__device__ int g_fill[NN];         // fill cursors
__device__ int g_rowptr[NN + 1];
__device__ int g_colidx[EE];

// ---------------------------------------------------------------------------
__global__ void detect_kernel(const long long* __restrict__ ei) {
    int is32 = 0;
    for (int i = 0; i < 256; i++) {
        long long v = ei[i];
        if (v < 0 || v >= NN) { is32 = 1; break; }
    }
    g_is32 = is32;
}

// ---------------------------------------------------------------------------
// CSR build: count -> scan -> fill.  Built once, used for all 3 layers.
// ---------------------------------------------------------------------------
__global__ void count_kernel(const void* __restrict__ ei) {
    int e = blockIdx.x * blockDim.x + threadIdx.x;
    if (e >= EE) return;
    int dst;
    if (g_is32) dst = __ldg((const int*)ei + EE + e);
    else        dst = (int)__ldg((const long long*)ei + EE + e);
    if ((unsigned)dst < NN) atomicAdd(&g_cnt[dst], 1);
}

__global__ __launch_bounds__(1024) void scan_kernel() {
    const int T = 1024;
    const int CH = (NN + T - 1) / T;          // 49
    __shared__ int tsum[T];
    const int tid = threadIdx.x;
    const int base = tid * CH;

    int s = 0;
    for (int i = 0; i < CH; i++) {
        int idx = base + i;
        if (idx < NN) s += g_cnt[idx];
    }
    tsum[tid] = s;
    __syncthreads();
    // Hillis-Steele inclusive scan
    for (int off = 1; off < T; off <<= 1) {
        int v = (tid >= off) ? tsum[tid - off] : 0;
        __syncthreads();
        tsum[tid] += v;
        __syncthreads();
    }
    int run = tsum[tid] - s;                  // exclusive prefix of this chunk
    for (int i = 0; i < CH; i++) {
        int idx = base + i;
        if (idx < NN) {
            int c = g_cnt[idx];
            g_rowptr[idx] = run;
            run += c;
        }
    }
    if (tid == T - 1) g_rowptr[NN] = run;
}

__global__ void fill_kernel(const void* __restrict__ ei) {
    int e = blockIdx.x * blockDim.x + threadIdx.x;
    if (e >= EE) return;
    int src, dst;
    if (g_is32) {
        src = __ldg((const int*)ei + e);
        dst = __ldg((const int*)ei + EE + e);
    } else {
        src = (int)__ldg((const long long*)ei + e);
        dst = (int)__ldg((const long long*)ei + EE + e);
    }
    if ((unsigned)src >= NN || (unsigned)dst >= NN) return;
    int pos = g_rowptr[dst] + atomicAdd(&g_fill[dst], 1);
    g_colidx[pos] = src;
}

// ---------------------------------------------------------------------------
// CSR gather: agg[i] = x[i] + sum_{j in N(i)} x[j].
// One warp per node; lane holds float2 column slice (256B coalesced per row).
// Neighbor indices loaded coalesced, distributed via shuffle.
// ---------------------------------------------------------------------------
__global__ __launch_bounds__(256) void gather_kernel(
    const float* __restrict__ x, float* __restrict__ agg)
{
    const int warp = (blockIdx.x * blockDim.x + threadIdx.x) >> 5;
    const int lane = threadIdx.x & 31;
    if (warp >= NN) return;
    const int node = warp;

    const int start = g_rowptr[node];
    const int end   = g_rowptr[node + 1];

    float2 acc = *(const float2*)(x + (size_t)node * 64 + lane * 2);

    for (int k = start; k < end; k += 32) {
        const int myidx = (k + lane < end) ? g_colidx[k + lane] : 0;
        const int m = min(32, end - k);
        #pragma unroll 4
        for (int j = 0; j < m; j++) {
            const int col = __shfl_sync(0xffffffffu, myidx, j);
            const float2 v = *(const float2*)(x + (size_t)col * 64 + lane * 2);
            acc.x += v.x;
            acc.y += v.y;
        }
    }
    *(float2*)(agg + (size_t)node * 64 + lane * 2) = acc;
}

// ---------------------------------------------------------------------------
// Register-tiled fused GIN MLP (unchanged from R5, ~50us/layer).
// ---------------------------------------------------------------------------
#define MLP_SHM_FLOATS 41344
#define MLP_SHM_BYTES  (MLP_SHM_FLOATS * 4)

__global__ __launch_bounds__(512) void mlp_kernel(
    const float* __restrict__ hin,
    const float* __restrict__ W1, const float* __restrict__ b1,
    const float* __restrict__ g1, const float* __restrict__ bt1,
    const float* __restrict__ m1, const float* __restrict__ v1,
    const float* __restrict__ W2, const float* __restrict__ b2,
    const float* __restrict__ gc, const float* __restrict__ bc,
    const float* __restrict__ mc, const float* __restrict__ vc,
    float* __restrict__ xout)
{
    extern __shared__ float sm[];
    float* W1s = sm;             // [64][128]   8192
    float* W2s = W1s + 8192;     // [128][64]   8192
    float* a1  = W2s + 8192;     // [128]
    float* c1  = a1 + 128;       // [128]
    float* a2  = c1 + 128;       // [64]
    float* c2  = a2 + 64;        // [64]
    float* xs  = c2 + 64;        // [128][64]   8192
    float* hs  = xs + 8192;      // [128][128]  16384

    const int tid  = threadIdx.x;
    const int warp = tid >> 5;
    const int lane = tid & 31;

    for (int i = tid; i < 8192; i += 512) W1s[i] = W1[i];
    for (int i = tid; i < 8192; i += 512) W2s[i] = W2[i];
    if (tid < 128) {
        float a = g1[tid] * rsqrtf(v1[tid] + BN_EPS);
        a1[tid] = a;
        c1[tid] = (b1[tid] - m1[tid]) * a + bt1[tid];
    } else if (tid < 192) {
        int j = tid - 128;
        float a = gc[j] * rsqrtf(vc[j] + BN_EPS);
        a2[j] = a;
        c2[j] = (b2[j] - mc[j]) * a + bc[j];
    }
    __syncthreads();

    const int ntiles = (NN + 127) >> 7;
    for (int tile = blockIdx.x; tile < ntiles; tile += gridDim.x) {
        const int base = tile << 7;

        for (int i = tid; i < 2048; i += 512) {
            int node = i >> 4;
            float4 v;
            if (base + node < NN)
                v = *(const float4*)(hin + (size_t)(base + node) * 64 + (i & 15) * 4);
            else
                v = make_float4(0.f, 0.f, 0.f, 0.f);
            *(float4*)(xs + i * 4) = v;
        }
        __syncthreads();

        // GEMM1
        {
            const int j0 = lane * 4;
            float4 acc[8];
            #pragma unroll
            for (int n = 0; n < 8; n++) acc[n] = make_float4(0.f, 0.f, 0.f, 0.f);
            const float* xrow = xs + (warp * 8) * 64;

            for (int k4 = 0; k4 < 16; k4++) {
                const float4 w0 = *(const float4*)(W1s + (k4 * 4 + 0) * 128 + j0);
                const float4 w1 = *(const float4*)(W1s + (k4 * 4 + 1) * 128 + j0);
                const float4 w2 = *(const float4*)(W1s + (k4 * 4 + 2) * 128 + j0);
                const float4 w3 = *(const float4*)(W1s + (k4 * 4 + 3) * 128 + j0);
                #pragma unroll
                for (int n = 0; n < 8; n++) {
                    const float4 xv = *(const float4*)(xrow + n * 64 + k4 * 4);
                    acc[n].x = fmaf(xv.x, w0.x, acc[n].x);
                    acc[n].y = fmaf(xv.x, w0.y, acc[n].y);
                    acc[n].z = fmaf(xv.x, w0.z, acc[n].z);
                    acc[n].w = fmaf(xv.x, w0.w, acc[n].w);
                    acc[n].x = fmaf(xv.y, w1.x, acc[n].x);
                    acc[n].y = fmaf(xv.y, w1.y, acc[n].y);
                    acc[n].z = fmaf(xv.y, w1.z, acc[n].z);
                    acc[n].w = fmaf(xv.y, w1.w, acc[n].w);
                    acc[n].x = fmaf(xv.z, w2.x, acc[n].x);
                    acc[n].y = fmaf(xv.z, w2.y, acc[n].y);
                    acc[n].z = fmaf(xv.z, w2.z, acc[n].z);
                    acc[n].w = fmaf(xv.z, w2.w, acc[n].w);
                    acc[n].x = fmaf(xv.w, w3.x, acc[n].x);
                    acc[n].y = fmaf(xv.w, w3.y, acc[n].y);
                    acc[n].z = fmaf(xv.w, w3.z, acc[n].z);
                    acc[n].w = fmaf(xv.w, w3.w, acc[n].w);
                }
            }
            const float4 A = *(const float4*)(a1 + j0);
            const float4 C = *(const float4*)(c1 + j0);
            #pragma unroll
            for (int n = 0; n < 8; n++) {
                float4 h;
                h.x = fmaxf(fmaf(acc[n].x, A.x, C.x), 0.f);
                h.y = fmaxf(fmaf(acc[n].y, A.y, C.y), 0.f);
                h.z = fmaxf(fmaf(acc[n].z, A.z, C.z), 0.f);
                h.w = fmaxf(fmaf(acc[n].w, A.w, C.w), 0.f);
                *(float4*)(hs + (warp * 8 + n) * 128 + j0) = h;
            }
        }
        __syncthreads();

        // GEMM2
        {
            const int j0 = lane * 2;
            float2 acc[8];
            #pragma unroll
            for (int n = 0; n < 8; n++) acc[n] = make_float2(0.f, 0.f);
            const float* hrow = hs + (warp * 8) * 128;

            for (int k4 = 0; k4 < 32; k4++) {
                const float2 w0 = *(const float2*)(W2s + (k4 * 4 + 0) * 64 + j0);
                const float2 w1 = *(const float2*)(W2s + (k4 * 4 + 1) * 64 + j0);
                const float2 w2 = *(const float2*)(W2s + (k4 * 4 + 2) * 64 + j0);
                const float2 w3 = *(const float2*)(W2s + (k4 * 4 + 3) * 64 + j0);
                #pragma unroll
                for (int n = 0; n < 8; n++) {
                    const float4 hv = *(const float4*)(hrow + n * 128 + k4 * 4);
                    acc[n].x = fmaf(hv.x, w0.x, acc[n].x);
                    acc[n].y = fmaf(hv.x, w0.y, acc[n].y);
                    acc[n].x = fmaf(hv.y, w1.x, acc[n].x);
                    acc[n].y = fmaf(hv.y, w1.y, acc[n].y);
                    acc[n].x = fmaf(hv.z, w2.x, acc[n].x);
                    acc[n].y = fmaf(hv.z, w2.y, acc[n].y);
                    acc[n].x = fmaf(hv.w, w3.x, acc[n].x);
                    acc[n].y = fmaf(hv.w, w3.y, acc[n].y);
                }
            }
            const float A0 = a2[j0], A1 = a2[j0 + 1];
            const float C0 = c2[j0], C1 = c2[j0 + 1];
            #pragma unroll
            for (int n = 0; n < 8; n++) {
                const int node = base + warp * 8 + n;
                if (node < NN) {
                    float2 o;
                    o.x = fmaxf(fmaf(acc[n].x, A0, C0), 0.f);
                    o.y = fmaxf(fmaf(acc[n].y, A1, C1), 0.f);
                    *(float2*)(xout + (size_t)node * 64 + j0) = o;
                }
            }
        }
        __syncthreads();
    }
}

// ---------------------------------------------------------------------------
// Head (unchanged).
// ---------------------------------------------------------------------------
#define HEAD_SHM_FLOATS 17576
#define HEAD_SHM_BYTES  (HEAD_SHM_FLOATS * 4)

__global__ __launch_bounds__(512) void head_kernel(
    const float* __restrict__ x,
    const float* __restrict__ lin1_W, const float* __restrict__ lin1_b,
    const float* __restrict__ g,  const float* __restrict__ b,
    const float* __restrict__ m,  const float* __restrict__ v,
    const float* __restrict__ lin2_W, const float* __restrict__ lin2_b,
    float* __restrict__ out)
{
    extern __shared__ float sm[];
    float* W1s = sm;             // [64][64]
    float* W2s = W1s + 4096;     // [64][40]
    float* a1  = W2s + 2560;     // [64]
    float* c1  = a1 + 64;        // [64]
    float* c2  = c1 + 64;        // [40]
    float* xs  = c2 + 40;        // [64][64]
    float* ts  = xs + 4096;      // [64][64]
    float* ls  = ts + 4096;      // [64][40]

    const int tid = threadIdx.x;

    for (int i = tid; i < 4096; i += 512) W1s[i] = lin1_W[i];
    for (int i = tid; i < 2560; i += 512) W2s[i] = lin2_W[i];
    if (tid < 64) {
        float a = g[tid] * rsqrtf(v[tid] + BN_EPS);
        a1[tid] = a;
        c1[tid] = (lin1_b[tid] - m[tid]) * a + b[tid];
    } else if (tid < 104) {
        c2[tid - 64] = lin2_b[tid - 64];
    }
    __syncthreads();

    const int ntiles = (NN + 63) >> 6;
    for (int tile = blockIdx.x; tile < ntiles; tile += gridDim.x) {
        const int base   = tile << 6;
        const int nvalid = min(64, NN - base);

        for (int i = tid; i < 64 * 64; i += 512) {
            int node = i >> 6;
            xs[i] = (node < nvalid) ? x[(long long)base * 64 + i] : 0.0f;
        }
        __syncthreads();

        for (int o = tid; o < 64 * 64; o += 512) {
            int node = o >> 6, j = o & 63;
            const float* xr = xs + node * 64;
            float acc = 0.0f;
            #pragma unroll
            for (int k = 0; k < 64; k++)
                acc = fmaf(xr[k], W1s[k * 64 + j], acc);
            ts[o] = fmaxf(acc * a1[j] + c1[j], 0.0f);
        }
        __syncthreads();

        for (int o = tid; o < 64 * CC; o += 512) {
            int node = o / CC, j = o - node * CC;
            const float* tr = ts + node * 64;
            float acc = c2[j];
            #pragma unroll
            for (int k = 0; k < 64; k++)
                acc = fmaf(tr[k], W2s[k * CC + j], acc);
            ls[o] = acc;
        }
        __syncthreads();

        if (tid < 64 && tid < nvalid) {
            const float* lr = ls + tid * CC;
            float mx = lr[0];
            #pragma unroll
            for (int c = 1; c < CC; c++) mx = fmaxf(mx, lr[c]);
            float s = 0.0f;
            #pragma unroll
            for (int c = 0; c < CC; c++) s += expf(lr[c] - mx);
            float lse = mx + logf(s);
            float* orow = out + (long long)(base + tid) * CC;
            #pragma unroll
            for (int c = 0; c < CC; c++) orow[c] = lr[c] - lse;
        }
        __syncthreads();
    }
}

// ---------------------------------------------------------------------------
extern "C" void kernel_launch(void* const* d_in, const int* in_sizes, int n_in,
                              void* d_out, int out_size) {
    const float* x = nullptr;
    const void*  ei = nullptr;
    const float* w24[2] = {nullptr, nullptr}; int n24 = 0;
    const float* p384[5] = {0};               int n384 = 0;
    const float* p192[5] = {0};               int n192 = 0;
    const float* p64[5]  = {0};               int n64 = 0;
    const float* lin1_W = nullptr;
    const float* lin2_W = nullptr;
    const float* lin2_b = nullptr;

    for (int i = 0; i < n_in; i++) {
        int s = in_sizes[i];
        const float* p = (const float*)d_in[i];
        if      (s == NN * FF)     x = p;
        else if (s == 2 * EE)      ei = d_in[i];
        else if (s == LL * FF * H2) { if (n24 < 2) w24[n24++] = p; }
        else if (s == LL * H2)     { if (n384 < 5) p384[n384++] = p; }
        else if (s == LL * HH)     { if (n192 < 5) p192[n192++] = p; }
        else if (s == HH * HH)     lin1_W = p;
        else if (s == HH)          { if (n64 < 5) p64[n64++] = p; }
        else if (s == HH * CC)     lin2_W = p;
        else if (s == CC)          lin2_b = p;
    }

    const float* W1s  = w24[0];
    const float* W2s  = w24[1];
    const float* b1s  = p384[0], *g1s = p384[1], *bt1s = p384[2],
               * m1s  = p384[3], *v1s = p384[4];
    const float* b2s  = p192[0], *gcs = p192[1], *bcs = p192[2],
               * mcs  = p192[3], *vcs = p192[4];
    const float* lin1_b = p64[0], *g_bn1 = p64[1], *b_bn1 = p64[2],
               * m_bn1  = p64[3], *v_bn1 = p64[4];

    if (!x || !ei || !W1s || !W2s || !lin1_W || !lin2_W || !lin2_b) return;

    float* gx;   cudaGetSymbolAddress((void**)&gx,   g_x);
    float* gagg; cudaGetSymbolAddress((void**)&gagg, g_agg);
    int*   gcnt; cudaGetSymbolAddress((void**)&gcnt, g_cnt);
    int*   gfil; cudaGetSymbolAddress((void**)&gfil, g_fill);

    cudaFuncSetAttribute(mlp_kernel,  cudaFuncAttributeMaxDynamicSharedMemorySize, MLP_SHM_BYTES);
    cudaFuncSetAttribute(head_kernel, cudaFuncAttributeMaxDynamicSharedMemorySize, HEAD_SHM_BYTES);

    // ---- CSR build (once per call, used for all 3 layers) ----
    detect_kernel<<<1, 1>>>((const long long*)ei);
    cudaMemsetAsync(gcnt, 0, NN * sizeof(int));
    cudaMemsetAsync(gfil, 0, NN * sizeof(int));
    count_kernel<<<(EE + 255) / 256, 256>>>(ei);
    scan_kernel<<<1, 1024>>>();
    fill_kernel<<<(EE + 255) / 256, 256>>>(ei);

    cudaMemcpyAsync(gx, x, (size_t)NN * FF * sizeof(float), cudaMemcpyDeviceToDevice);

    const int gather_blocks = (NN * 32 + 255) / 256;   // one warp per node

    for (int l = 0; l < LL; l++) {
        gather_kernel<<<gather_blocks, 256>>>(gx, gagg);
        mlp_kernel<<<148, 512, MLP_SHM_BYTES>>>(
            gagg,
            W1s + (size_t)l * FF * H2,  b1s + (size_t)l * H2,
            g1s + (size_t)l * H2,       bt1s + (size_t)l * H2,
            m1s + (size_t)l * H2,       v1s + (size_t)l * H2,
            W2s + (size_t)l * H2 * HH,  b2s + (size_t)l * HH,
            gcs + (size_t)l * HH,       bcs + (size_t)l * HH,
            mcs + (size_t)l * HH,       vcs + (size_t)l * HH,
            gx);
    }

    head_kernel<<<148, 512, HEAD_SHM_BYTES>>>(
        gx, lin1_W, lin1_b, g_bn1, b_bn1, m_bn1, v_bn1, lin2_W, lin2_b,
        (float*)d_out);
}

// round 7
// speedup vs baseline: 1.4931x; 1.0279x over previous
#include <cuda_runtime.h>
#include <cstdint>

#define NN 50000
#define EE 800000
#define FF 64
#define HH 64
#define H2 128
#define CC 40
#define LL 3
#define BN_EPS 1e-5f

__device__ __align__(16) float g_x[NN * FF];     // current node features
__device__ __align__(16) float g_agg[NN * FF];   // x + neighbor-sum buffer
__device__ int g_is32;

// CSR scratch
__device__ int g_cnt[NN];
__device__ int g_fill[NN];
__device__ int g_rowptr[NN + 1];
__device__ int g_colidx[EE];

// ---------------------------------------------------------------------------
// Parallel dtype detect: one block, each thread checks one int64 word.
// int32 data read as int64 -> huge/garbage values outside [0, NN).
// ---------------------------------------------------------------------------
__global__ void detect_kernel(const long long* __restrict__ ei) {
    long long v = ei[threadIdx.x];
    int bad = (v < 0 || v >= NN) ? 1 : 0;
    int any = __syncthreads_or(bad);
    if (threadIdx.x == 0) g_is32 = any;
}

// ---------------------------------------------------------------------------
// CSR build: count -> scan -> fill. 4 edges/thread, strided for coalescing.
// ---------------------------------------------------------------------------
#define CSR_THREADS ((EE + 3) / 4)

__global__ void count_kernel(const void* __restrict__ ei) {
    const int t = blockIdx.x * blockDim.x + threadIdx.x;
    #pragma unroll
    for (int u = 0; u < 4; u++) {
        int e = t + u * CSR_THREADS;
        if (e >= EE) break;
        int dst;
        if (g_is32) dst = __ldg((const int*)ei + EE + e);
        else        dst = (int)__ldg((const long long*)ei + EE + e);
        if ((unsigned)dst < NN) atomicAdd(&g_cnt[dst], 1);
    }
}

__global__ __launch_bounds__(1024) void scan_kernel() {
    const int T = 1024;
    const int CH = (NN + T - 1) / T;          // 49
    __shared__ int tsum[T];
    const int tid = threadIdx.x;
    const int base = tid * CH;

    int s = 0;
    for (int i = 0; i < CH; i++) {
        int idx = base + i;
        if (idx < NN) s += g_cnt[idx];
    }
    tsum[tid] = s;
    __syncthreads();
    for (int off = 1; off < T; off <<= 1) {
        int v = (tid >= off) ? tsum[tid - off] : 0;
        __syncthreads();
        tsum[tid] += v;
        __syncthreads();
    }
    int run = tsum[tid] - s;
    for (int i = 0; i < CH; i++) {
        int idx = base + i;
        if (idx < NN) {
            int c = g_cnt[idx];
            g_rowptr[idx] = run;
            run += c;
        }
    }
    if (tid == T - 1) g_rowptr[NN] = run;
}

__global__ void fill_kernel(const void* __restrict__ ei) {
    const int t = blockIdx.x * blockDim.x + threadIdx.x;
    #pragma unroll
    for (int u = 0; u < 4; u++) {
        int e = t + u * CSR_THREADS;
        if (e >= EE) break;
        int src, dst;
        if (g_is32) {
            src = __ldg((const int*)ei + e);
            dst = __ldg((const int*)ei + EE + e);
        } else {
            src = (int)__ldg((const long long*)ei + e);
            dst = (int)__ldg((const long long*)ei + EE + e);
        }
        if ((unsigned)src >= NN || (unsigned)dst >= NN) continue;
        int pos = g_rowptr[dst] + atomicAdd(&g_fill[dst], 1);
        g_colidx[pos] = src;
    }
}

// ---------------------------------------------------------------------------
// CSR gather v2: agg[i] = x[i] + sum_{j in N(i)} x[j].
// One warp per node. Lane loads float4 -> 16 lanes cover the 64-float row.
// The two half-warps process two neighbors concurrently; x4 unroll gives 8
// independent 16B row-loads in flight per warp (latency hiding).
// ---------------------------------------------------------------------------
__global__ __launch_bounds__(256) void gather_kernel(
    const float* __restrict__ x, float* __restrict__ agg)
{
    const int warp = (blockIdx.x * blockDim.x + threadIdx.x) >> 5;
    if (warp >= NN) return;
    const int lane = threadIdx.x & 31;
    const int half = lane >> 4;        // 0 or 1
    const int sub  = lane & 15;        // float4 slot within row

    const int start = g_rowptr[warp];
    const int end   = g_rowptr[warp + 1];

    float4 acc = make_float4(0.f, 0.f, 0.f, 0.f);
    if (half == 0)
        acc = *(const float4*)(x + (size_t)warp * 64 + sub * 4);

    int k = start + half;              // half h takes neighbors start+h, +2, ...
    for (; k + 6 < end; k += 8) {
        const int i0 = __ldg(g_colidx + k);
        const int i1 = __ldg(g_colidx + k + 2);
        const int i2 = __ldg(g_colidx + k + 4);
        const int i3 = __ldg(g_colidx + k + 6);
        const float4 v0 = *(const float4*)(x + (size_t)i0 * 64 + sub * 4);
        const float4 v1 = *(const float4*)(x + (size_t)i1 * 64 + sub * 4);
        const float4 v2 = *(const float4*)(x + (size_t)i2 * 64 + sub * 4);
        const float4 v3 = *(const float4*)(x + (size_t)i3 * 64 + sub * 4);
        acc.x += v0.x + v1.x + v2.x + v3.x;
        acc.y += v0.y + v1.y + v2.y + v3.y;
        acc.z += v0.z + v1.z + v2.z + v3.z;
        acc.w += v0.w + v1.w + v2.w + v3.w;
    }
    for (; k < end; k += 2) {
        const int i = __ldg(g_colidx + k);
        const float4 v = *(const float4*)(x + (size_t)i * 64 + sub * 4);
        acc.x += v.x; acc.y += v.y; acc.z += v.z; acc.w += v.w;
    }

    // combine the two halves (same columns, different neighbor subsets)
    acc.x += __shfl_xor_sync(0xffffffffu, acc.x, 16);
    acc.y += __shfl_xor_sync(0xffffffffu, acc.y, 16);
    acc.z += __shfl_xor_sync(0xffffffffu, acc.z, 16);
    acc.w += __shfl_xor_sync(0xffffffffu, acc.w, 16);

    if (half == 0)
        *(float4*)(agg + (size_t)warp * 64 + sub * 4) = acc;
}

// ---------------------------------------------------------------------------
// Register-tiled fused GIN MLP (unchanged, ~50us/layer).
// ---------------------------------------------------------------------------
#define MLP_SHM_FLOATS 41344
#define MLP_SHM_BYTES  (MLP_SHM_FLOATS * 4)

__global__ __launch_bounds__(512) void mlp_kernel(
    const float* __restrict__ hin,
    const float* __restrict__ W1, const float* __restrict__ b1,
    const float* __restrict__ g1, const float* __restrict__ bt1,
    const float* __restrict__ m1, const float* __restrict__ v1,
    const float* __restrict__ W2, const float* __restrict__ b2,
    const float* __restrict__ gc, const float* __restrict__ bc,
    const float* __restrict__ mc, const float* __restrict__ vc,
    float* __restrict__ xout)
{
    extern __shared__ float sm[];
    float* W1s = sm;             // [64][128]   8192
    float* W2s = W1s + 8192;     // [128][64]   8192
    float* a1  = W2s + 8192;     // [128]
    float* c1  = a1 + 128;       // [128]
    float* a2  = c1 + 128;       // [64]
    float* c2  = a2 + 64;        // [64]
    float* xs  = c2 + 64;        // [128][64]   8192
    float* hs  = xs + 8192;      // [128][128]  16384

    const int tid  = threadIdx.x;
    const int warp = tid >> 5;
    const int lane = tid & 31;

    for (int i = tid; i < 8192; i += 512) W1s[i] = W1[i];
    for (int i = tid; i < 8192; i += 512) W2s[i] = W2[i];
    if (tid < 128) {
        float a = g1[tid] * rsqrtf(v1[tid] + BN_EPS);
        a1[tid] = a;
        c1[tid] = (b1[tid] - m1[tid]) * a + bt1[tid];
    } else if (tid < 192) {
        int j = tid - 128;
        float a = gc[j] * rsqrtf(vc[j] + BN_EPS);
        a2[j] = a;
        c2[j] = (b2[j] - mc[j]) * a + bc[j];
    }
    __syncthreads();

    const int ntiles = (NN + 127) >> 7;
    for (int tile = blockIdx.x; tile < ntiles; tile += gridDim.x) {
        const int base = tile << 7;

        for (int i = tid; i < 2048; i += 512) {
            int node = i >> 4;
            float4 v;
            if (base + node < NN)
                v = *(const float4*)(hin + (size_t)(base + node) * 64 + (i & 15) * 4);
            else
                v = make_float4(0.f, 0.f, 0.f, 0.f);
            *(float4*)(xs + i * 4) = v;
        }
        __syncthreads();

        // GEMM1
        {
            const int j0 = lane * 4;
            float4 acc[8];
            #pragma unroll
            for (int n = 0; n < 8; n++) acc[n] = make_float4(0.f, 0.f, 0.f, 0.f);
            const float* xrow = xs + (warp * 8) * 64;

            for (int k4 = 0; k4 < 16; k4++) {
                const float4 w0 = *(const float4*)(W1s + (k4 * 4 + 0) * 128 + j0);
                const float4 w1 = *(const float4*)(W1s + (k4 * 4 + 1) * 128 + j0);
                const float4 w2 = *(const float4*)(W1s + (k4 * 4 + 2) * 128 + j0);
                const float4 w3 = *(const float4*)(W1s + (k4 * 4 + 3) * 128 + j0);
                #pragma unroll
                for (int n = 0; n < 8; n++) {
                    const float4 xv = *(const float4*)(xrow + n * 64 + k4 * 4);
                    acc[n].x = fmaf(xv.x, w0.x, acc[n].x);
                    acc[n].y = fmaf(xv.x, w0.y, acc[n].y);
                    acc[n].z = fmaf(xv.x, w0.z, acc[n].z);
                    acc[n].w = fmaf(xv.x, w0.w, acc[n].w);
                    acc[n].x = fmaf(xv.y, w1.x, acc[n].x);
                    acc[n].y = fmaf(xv.y, w1.y, acc[n].y);
                    acc[n].z = fmaf(xv.y, w1.z, acc[n].z);
                    acc[n].w = fmaf(xv.y, w1.w, acc[n].w);
                    acc[n].x = fmaf(xv.z, w2.x, acc[n].x);
                    acc[n].y = fmaf(xv.z, w2.y, acc[n].y);
                    acc[n].z = fmaf(xv.z, w2.z, acc[n].z);
                    acc[n].w = fmaf(xv.z, w2.w, acc[n].w);
                    acc[n].x = fmaf(xv.w, w3.x, acc[n].x);
                    acc[n].y = fmaf(xv.w, w3.y, acc[n].y);
                    acc[n].z = fmaf(xv.w, w3.z, acc[n].z);
                    acc[n].w = fmaf(xv.w, w3.w, acc[n].w);
                }
            }
            const float4 A = *(const float4*)(a1 + j0);
            const float4 C = *(const float4*)(c1 + j0);
            #pragma unroll
            for (int n = 0; n < 8; n++) {
                float4 h;
                h.x = fmaxf(fmaf(acc[n].x, A.x, C.x), 0.f);
                h.y = fmaxf(fmaf(acc[n].y, A.y, C.y), 0.f);
                h.z = fmaxf(fmaf(acc[n].z, A.z, C.z), 0.f);
                h.w = fmaxf(fmaf(acc[n].w, A.w, C.w), 0.f);
                *(float4*)(hs + (warp * 8 + n) * 128 + j0) = h;
            }
        }
        __syncthreads();

        // GEMM2
        {
            const int j0 = lane * 2;
            float2 acc[8];
            #pragma unroll
            for (int n = 0; n < 8; n++) acc[n] = make_float2(0.f, 0.f);
            const float* hrow = hs + (warp * 8) * 128;

            for (int k4 = 0; k4 < 32; k4++) {
                const float2 w0 = *(const float2*)(W2s + (k4 * 4 + 0) * 64 + j0);
                const float2 w1 = *(const float2*)(W2s + (k4 * 4 + 1) * 64 + j0);
                const float2 w2 = *(const float2*)(W2s + (k4 * 4 + 2) * 64 + j0);
                const float2 w3 = *(const float2*)(W2s + (k4 * 4 + 3) * 64 + j0);
                #pragma unroll
                for (int n = 0; n < 8; n++) {
                    const float4 hv = *(const float4*)(hrow + n * 128 + k4 * 4);
                    acc[n].x = fmaf(hv.x, w0.x, acc[n].x);
                    acc[n].y = fmaf(hv.x, w0.y, acc[n].y);
                    acc[n].x = fmaf(hv.y, w1.x, acc[n].x);
                    acc[n].y = fmaf(hv.y, w1.y, acc[n].y);
                    acc[n].x = fmaf(hv.z, w2.x, acc[n].x);
                    acc[n].y = fmaf(hv.z, w2.y, acc[n].y);
                    acc[n].x = fmaf(hv.w, w3.x, acc[n].x);
                    acc[n].y = fmaf(hv.w, w3.y, acc[n].y);
                }
            }
            const float A0 = a2[j0], A1 = a2[j0 + 1];
            const float C0 = c2[j0], C1 = c2[j0 + 1];
            #pragma unroll
            for (int n = 0; n < 8; n++) {
                const int node = base + warp * 8 + n;
                if (node < NN) {
                    float2 o;
                    o.x = fmaxf(fmaf(acc[n].x, A0, C0), 0.f);
                    o.y = fmaxf(fmaf(acc[n].y, A1, C1), 0.f);
                    *(float2*)(xout + (size_t)node * 64 + j0) = o;
                }
            }
        }
        __syncthreads();
    }
}

// ---------------------------------------------------------------------------
// Head (unchanged).
// ---------------------------------------------------------------------------
#define HEAD_SHM_FLOATS 17576
#define HEAD_SHM_BYTES  (HEAD_SHM_FLOATS * 4)

__global__ __launch_bounds__(512) void head_kernel(
    const float* __restrict__ x,
    const float* __restrict__ lin1_W, const float* __restrict__ lin1_b,
    const float* __restrict__ g,  const float* __restrict__ b,
    const float* __restrict__ m,  const float* __restrict__ v,
    const float* __restrict__ lin2_W, const float* __restrict__ lin2_b,
    float* __restrict__ out)
{
    extern __shared__ float sm[];
    float* W1s = sm;             // [64][64]
    float* W2s = W1s + 4096;     // [64][40]
    float* a1  = W2s + 2560;     // [64]
    float* c1  = a1 + 64;        // [64]
    float* c2  = c1 + 64;        // [40]
    float* xs  = c2 + 40;        // [64][64]
    float* ts  = xs + 4096;      // [64][64]
    float* ls  = ts + 4096;      // [64][40]

    const int tid = threadIdx.x;

    for (int i = tid; i < 4096; i += 512) W1s[i] = lin1_W[i];
    for (int i = tid; i < 2560; i += 512) W2s[i] = lin2_W[i];
    if (tid < 64) {
        float a = g[tid] * rsqrtf(v[tid] + BN_EPS);
        a1[tid] = a;
        c1[tid] = (lin1_b[tid] - m[tid]) * a + b[tid];
    } else if (tid < 104) {
        c2[tid - 64] = lin2_b[tid - 64];
    }
    __syncthreads();

    const int ntiles = (NN + 63) >> 6;
    for (int tile = blockIdx.x; tile < ntiles; tile += gridDim.x) {
        const int base   = tile << 6;
        const int nvalid = min(64, NN - base);

        for (int i = tid; i < 64 * 64; i += 512) {
            int node = i >> 6;
            xs[i] = (node < nvalid) ? x[(long long)base * 64 + i] : 0.0f;
        }
        __syncthreads();

        for (int o = tid; o < 64 * 64; o += 512) {
            int node = o >> 6, j = o & 63;
            const float* xr = xs + node * 64;
            float acc = 0.0f;
            #pragma unroll
            for (int k = 0; k < 64; k++)
                acc = fmaf(xr[k], W1s[k * 64 + j], acc);
            ts[o] = fmaxf(acc * a1[j] + c1[j], 0.0f);
        }
        __syncthreads();

        for (int o = tid; o < 64 * CC; o += 512) {
            int node = o / CC, j = o - node * CC;
            const float* tr = ts + node * 64;
            float acc = c2[j];
            #pragma unroll
            for (int k = 0; k < 64; k++)
                acc = fmaf(tr[k], W2s[k * CC + j], acc);
            ls[o] = acc;
        }
        __syncthreads();

        if (tid < 64 && tid < nvalid) {
            const float* lr = ls + tid * CC;
            float mx = lr[0];
            #pragma unroll
            for (int c = 1; c < CC; c++) mx = fmaxf(mx, lr[c]);
            float s = 0.0f;
            #pragma unroll
            for (int c = 0; c < CC; c++) s += expf(lr[c] - mx);
            float lse = mx + logf(s);
            float* orow = out + (long long)(base + tid) * CC;
            #pragma unroll
            for (int c = 0; c < CC; c++) orow[c] = lr[c] - lse;
        }
        __syncthreads();
    }
}

// ---------------------------------------------------------------------------
extern "C" void kernel_launch(void* const* d_in, const int* in_sizes, int n_in,
                              void* d_out, int out_size) {
    const float* x = nullptr;
    const void*  ei = nullptr;
    const float* w24[2] = {nullptr, nullptr}; int n24 = 0;
    const float* p384[5] = {0};               int n384 = 0;
    const float* p192[5] = {0};               int n192 = 0;
    const float* p64[5]  = {0};               int n64 = 0;
    const float* lin1_W = nullptr;
    const float* lin2_W = nullptr;
    const float* lin2_b = nullptr;

    for (int i = 0; i < n_in; i++) {
        int s = in_sizes[i];
        const float* p = (const float*)d_in[i];
        if      (s == NN * FF)     x = p;
        else if (s == 2 * EE)      ei = d_in[i];
        else if (s == LL * FF * H2) { if (n24 < 2) w24[n24++] = p; }
        else if (s == LL * H2)     { if (n384 < 5) p384[n384++] = p; }
        else if (s == LL * HH)     { if (n192 < 5) p192[n192++] = p; }
        else if (s == HH * HH)     lin1_W = p;
        else if (s == HH)          { if (n64 < 5) p64[n64++] = p; }
        else if (s == HH * CC)     lin2_W = p;
        else if (s == CC)          lin2_b = p;
    }

    const float* W1s  = w24[0];
    const float* W2s  = w24[1];
    const float* b1s  = p384[0], *g1s = p384[1], *bt1s = p384[2],
               * m1s  = p384[3], *v1s = p384[4];
    const float* b2s  = p192[0], *gcs = p192[1], *bcs = p192[2],
               * mcs  = p192[3], *vcs = p192[4];
    const float* lin1_b = p64[0], *g_bn1 = p64[1], *b_bn1 = p64[2],
               * m_bn1  = p64[3], *v_bn1 = p64[4];

    if (!x || !ei || !W1s || !W2s || !lin1_W || !lin2_W || !lin2_b) return;

    float* gx;   cudaGetSymbolAddress((void**)&gx,   g_x);
    float* gagg; cudaGetSymbolAddress((void**)&gagg, g_agg);
    int*   gcnt; cudaGetSymbolAddress((void**)&gcnt, g_cnt);
    int*   gfil; cudaGetSymbolAddress((void**)&gfil, g_fill);

    cudaFuncSetAttribute(mlp_kernel,  cudaFuncAttributeMaxDynamicSharedMemorySize, MLP_SHM_BYTES);
    cudaFuncSetAttribute(head_kernel, cudaFuncAttributeMaxDynamicSharedMemorySize, HEAD_SHM_BYTES);

    // ---- CSR build (once, reused all layers) ----
    detect_kernel<<<1, 256>>>((const long long*)ei);
    cudaMemsetAsync(gcnt, 0, NN * sizeof(int));
    cudaMemsetAsync(gfil, 0, NN * sizeof(int));
    const int csr_blocks = (CSR_THREADS + 255) / 256;
    count_kernel<<<csr_blocks, 256>>>(ei);
    scan_kernel<<<1, 1024>>>();
    fill_kernel<<<csr_blocks, 256>>>(ei);

    cudaMemcpyAsync(gx, x, (size_t)NN * FF * sizeof(float), cudaMemcpyDeviceToDevice);

    const int gather_blocks = (NN * 32 + 255) / 256;   // one warp per node

    for (int l = 0; l < LL; l++) {
        gather_kernel<<<gather_blocks, 256>>>(gx, gagg);
        mlp_kernel<<<148, 512, MLP_SHM_BYTES>>>(
            gagg,
            W1s + (size_t)l * FF * H2,  b1s + (size_t)l * H2,
            g1s + (size_t)l * H2,       bt1s + (size_t)l * H2,
            m1s + (size_t)l * H2,       v1s + (size_t)l * H2,
            W2s + (size_t)l * H2 * HH,  b2s + (size_t)l * HH,
            gcs + (size_t)l * HH,       bcs + (size_t)l * HH,
            mcs + (size_t)l * HH,       vcs + (size_t)l * HH,
            gx);
    }

    head_kernel<<<148, 512, HEAD_SHM_BYTES>>>(
        gx, lin1_W, lin1_b, g_bn1, b_bn1, m_bn1, v_bn1, lin2_W, lin2_b,
        (float*)d_out);
}